// round 10
// baseline (speedup 1.0000x reference)
#include <cuda_runtime.h>
#include <cuda_fp16.h>
#include <math.h>
#include <stdint.h>

// Problem constants
#define BB 128      // batch
#define SS 512      // seq len
#define II 512      // input dim
#define HH 1024     // hidden dim
#define GG 4096     // 4*H (gates)

#define NB 128      // persistent CTAs: 64 col-groups x 2 batch halves
#define NT 512      // threads per CTA (16 warps)

// ---------------------------------------------------------------------------
// Device scratch
// ---------------------------------------------------------------------------
__device__ __half   g_xwh[(size_t)SS * BB * GG];  // (s, b, n'=4h+g) fp16 : 0.5 GiB
__device__ __half   g_Uh[(size_t)GG * HH];        // U re-laid: [n'][k], fp16
__device__ __half   g_Whk[(size_t)GG * II];       // W re-laid: [n'][k], fp16
__device__ __half   g_xh[(size_t)BB * SS * II];   // x in fp16
__device__ float    g_biasI[GG];                  // bias interleaved n'=4h+g
__device__ __half   g_hbuf[2][BB * HH];           // double-buffered hidden (fp16)
__device__ unsigned g_flags[2][64][8];            // per (half, col-group) progress,
                                                  // 32B padded; [mh][cx][0] = steps done

// ---------------------------------------------------------------------------
// Helpers
// ---------------------------------------------------------------------------
__device__ __forceinline__ float sigm(float v) { return 1.0f / (1.0f + __expf(-v)); }
__device__ __forceinline__ uint32_t smem_u32(const void* p) {
    uint32_t a;
    asm("{ .reg .u64 t; cvta.to.shared.u64 t, %1; cvt.u32.u64 %0, t; }"
        : "=r"(a) : "l"(p));
    return a;
}
__device__ __forceinline__ void mma_f16(float* d, const uint32_t* a, const uint32_t* b) {
    asm volatile(
        "mma.sync.aligned.m16n8k16.row.col.f32.f16.f16.f32 "
        "{%0,%1,%2,%3}, {%4,%5,%6,%7}, {%8,%9}, {%0,%1,%2,%3};"
        : "+f"(d[0]), "+f"(d[1]), "+f"(d[2]), "+f"(d[3])
        : "r"(a[0]), "r"(a[1]), "r"(a[2]), "r"(a[3]), "r"(b[0]), "r"(b[1]));
}
__device__ __forceinline__ void ldsm4(uint32_t* r, uint32_t addr) {
    asm volatile("ldmatrix.sync.aligned.m8n8.x4.shared.b16 {%0,%1,%2,%3}, [%4];"
        : "=r"(r[0]), "=r"(r[1]), "=r"(r[2]), "=r"(r[3]) : "r"(addr));
}
__device__ __forceinline__ void cp16(uint32_t s, const void* g) {
    asm volatile("cp.async.cg.shared.global [%0], [%1], 16;" :: "r"(s), "l"(g));
}
#define CP_COMMIT() asm volatile("cp.async.commit_group;" ::: "memory")
#define CP_WAIT1()  asm volatile("cp.async.wait_group 1;" ::: "memory")
#define CP_WAIT0()  asm volatile("cp.async.wait_group 0;" ::: "memory")

// ---------------------------------------------------------------------------
// init: zero h buffers + flags; interleaved bias
// ---------------------------------------------------------------------------
__global__ void lstm_init(const float* __restrict__ bias) {
    int idx = blockIdx.x * blockDim.x + threadIdx.x; // 131072 threads
    ((uint32_t*)g_hbuf)[idx] = 0u;                   // both 256KB buffers
    if (idx < 1024) ((unsigned*)g_flags)[idx] = 0u;  // reset every replay
    if (idx < GG) {
        int h = idx >> 2, g = idx & 3;
        g_biasI[idx] = bias[g * HH + h];
    }
}

// ---------------------------------------------------------------------------
// Preps: fp16 conversions / re-layouts
// ---------------------------------------------------------------------------
__global__ void ut_prep(const float* __restrict__ U) {
    size_t idx = (size_t)blockIdx.x * 256 + threadIdx.x; // 4M, idx = n'*1024+k
    int n = (int)(idx >> 10);
    int k = (int)(idx & 1023);
    int h = n >> 2, g = n & 3;
    g_Uh[idx] = __float2half_rn(U[(size_t)k * GG + g * HH + h]);
}
__global__ void wt_prep(const float* __restrict__ W) {
    size_t idx = (size_t)blockIdx.x * 256 + threadIdx.x; // 2M, idx = n'*512+k
    int n = (int)(idx >> 9);
    int k = (int)(idx & 511);
    int h = n >> 2, g = n & 3;
    g_Whk[idx] = __float2half_rn(W[(size_t)k * GG + g * HH + h]);
}
__global__ void x_prep(const float* __restrict__ x) {
    size_t i4 = (size_t)blockIdx.x * 256 + threadIdx.x; // 8.4M, 4 floats each
    float4 v = *(const float4*)(x + i4 * 4);
    __half2 a = __floats2half2_rn(v.x, v.y);
    __half2 b = __floats2half2_rn(v.z, v.w);
    *(uint2*)(g_xh + i4 * 4) = make_uint2(*(uint32_t*)&a, *(uint32_t*)&b);
}

// ---------------------------------------------------------------------------
// GEMM 1 via mma.sync fp16: xW = x @ W + bias -> g_xwh (fp16, interleaved n')
// ---------------------------------------------------------------------------
#define G_RB 80     // row bytes (32 data halves + 8 pad)

__global__ __launch_bounds__(256) void gemm_xw_mma(void)
{
    __shared__ __half As[128 * 40];
    __shared__ __half Bs[128 * 40];
    const uint32_t sA = smem_u32(As);
    const uint32_t sB = smem_u32(Bs);

    const int tid  = threadIdx.x;
    const int wid  = tid >> 5;
    const int lane = tid & 31;
    const int qr = lane >> 2;
    const int qc = lane & 3;

    const int m0 = blockIdx.x * 128;
    const int n0 = blockIdx.y * 128;
    const int m0w = (wid & 1) * 64;
    const int n0w = (wid >> 1) * 32;

    const uint32_t offA = (uint32_t)((m0w + (lane & 15)) * G_RB + (lane >> 4) * 16);
    const uint32_t offB = (uint32_t)((n0w + ((lane >> 4) << 3) + (lane & 7)) * G_RB
                                     + ((lane >> 3) & 1) * 16);

    float acc[4][4][4];
#pragma unroll
    for (int i = 0; i < 4; i++)
#pragma unroll
        for (int j = 0; j < 4; j++)
#pragma unroll
            for (int q = 0; q < 4; q++) acc[i][j][q] = 0.0f;

    for (int k0 = 0; k0 < II; k0 += 32) {
#pragma unroll
        for (int i = 0; i < 2; i++) {
            int f = i * 256 + tid;
            int r = f >> 2, c = f & 3;
            *(uint4*)((char*)As + r * G_RB + c * 16) =
                *(const uint4*)&g_xh[(size_t)(m0 + r) * II + k0 + c * 8];
        }
#pragma unroll
        for (int i = 0; i < 2; i++) {
            int f = i * 256 + tid;
            int r = f >> 2, c = f & 3;
            *(uint4*)((char*)Bs + r * G_RB + c * 16) =
                *(const uint4*)&g_Whk[(size_t)(n0 + r) * II + k0 + c * 8];
        }
        __syncthreads();

#pragma unroll
        for (int kk = 0; kk < 2; kk++) {
            const uint32_t kb = kk * 32;
            uint32_t a[4][4], b[2][4];
#pragma unroll
            for (int mt = 0; mt < 4; mt++)
                ldsm4(a[mt], sA + offA + mt * 16 * G_RB + kb);
            ldsm4(b[0], sB + offB + kb);
            ldsm4(b[1], sB + offB + 16 * G_RB + kb);
#pragma unroll
            for (int mt = 0; mt < 4; mt++)
#pragma unroll
                for (int nt = 0; nt < 4; nt++)
                    mma_f16(acc[mt][nt], a[mt], &b[nt >> 1][(nt & 1) * 2]);
        }
        __syncthreads();
    }

    // epilogue: + biasI, fp16 pack, scatter to g_xwh[(s*BB+b)*GG + n']
#pragma unroll
    for (int nt = 0; nt < 4; nt++) {
        int col = n0 + n0w + nt * 8 + qc * 2;
        float2 bv = *(const float2*)&g_biasI[col];
#pragma unroll
        for (int mt = 0; mt < 4; mt++) {
            int r1 = m0 + m0w + mt * 16 + qr;
            int r2 = r1 + 8;
            int b1 = r1 >> 9, s1 = r1 & 511;
            int b2 = r2 >> 9, s2 = r2 & 511;
            size_t d1 = ((size_t)s1 * BB + b1) * GG + col;
            size_t d2 = ((size_t)s2 * BB + b2) * GG + col;
            *(__half2*)&g_xwh[d1] = __floats2half2_rn(acc[mt][nt][0] + bv.x,
                                                      acc[mt][nt][1] + bv.y);
            *(__half2*)&g_xwh[d2] = __floats2half2_rn(acc[mt][nt][2] + bv.x,
                                                      acc[mt][nt][3] + bv.y);
        }
    }
}

// ---------------------------------------------------------------------------
// Persistent recurrence: 128 CTAs, 16 warps, NO global barrier.
// Fine-grained flags: chunk kc reads h cols [kc*128, kc*128+128) produced by
// col-groups cx in [8kc, 8kc+8). Before issuing that chunk's cp.async, the
// CTA waits flag[mh][cx] >= t for those 8 producers. Buffer safety: a CTA's
// epilogue (writes hbuf[(t+1)&1]) follows all 8 chunk waits, whose union
// covers all 64 producers >= t, bounding inter-CTA skew to < 1 step.
// ---------------------------------------------------------------------------
#define KC       128
#define NCHUNK   8
#define A_RB     272                    // 64 rows x (256 data + 16 pad) bytes
#define A_STGB   (64 * A_RB)            // 17408
#define B_RB     2064
#define B_OFF    (3 * A_STGB)           // 52224
#define RSM_BYTES (B_OFF + 64 * B_RB)   // 184320

__global__ __launch_bounds__(NT, 1) void lstm_mma(float* __restrict__ out)
{
    extern __shared__ char smc[];
    const uint32_t sb0 = smem_u32(smc);

    const int tid  = threadIdx.x;
    const int wid  = tid >> 5;
    const int lane = tid & 31;
    const int qr = lane >> 2;
    const int qc = lane & 3;
    const int cx = blockIdx.x >> 1;     // column group 0..63
    const int mh = blockIdx.x & 1;      // batch half 0..1

    const int m0w = (wid & 3) * 16;     // warp rows (0,16,32,48)
    const int n0w = (wid >> 2) * 16;    // warp cols (0,16,32,48)

    // ldmatrix lane offsets
    const uint32_t offA = (uint32_t)((m0w + (lane & 15)) * A_RB + (lane >> 4) * 16);
    const uint32_t offB = (uint32_t)(B_OFF +
        (n0w + ((lane >> 4) << 3) + (lane & 7)) * B_RB + ((lane >> 3) & 1) * 16);

    const __half* Up = g_Uh + (size_t)cx * 64 * HH;
    const int mrow0 = mh * 64;          // first batch row of this CTA

    // cell-ownership mapping (matches MMA accumulator layout)
    const int odd   = qc & 1;
    const int urow  = m0w + qr + (odd ? 8 : 0);          // local batch row
    const int hl0   = (n0w >> 2) + (qc >> 1);            // nt=0 hidden unit

    float c_reg[2], oacc[2];
    c_reg[0] = c_reg[1] = oacc[0] = oacc[1] = 0.f;

    // ---- one-time: U slice into persistent smem (8192 x 16B, 16/thread) ----
#pragma unroll
    for (int i = 0; i < 16; i++) {
        int f = i * 512 + tid;
        int r = f >> 7, c = f & 127;
        cp16(sb0 + (uint32_t)(B_OFF + r * B_RB + c * 16),
             Up + (size_t)r * HH + c * 8);
    }
    CP_COMMIT();
    CP_WAIT0();
    __syncthreads();

    for (int t = 0; t < SS; t++) {
        const __half* hcur = g_hbuf[t & 1] + (size_t)mrow0 * HH;
        const unsigned tgt = (unsigned)t;

        // prefetch xw (fp16): 4 gates per cell, 2 cells per lane
        uint2 xwr0, xwr1;
        {
            const __half* xp = g_xwh + ((size_t)t * BB + mrow0 + urow) * GG
                             + cx * 64;
            xwr0 = __ldg((const uint2*)(xp + hl0 * 4));
            xwr1 = __ldg((const uint2*)(xp + (hl0 + 2) * 4));
        }

        float acc[2][4];
#pragma unroll
        for (int j = 0; j < 2; j++)
#pragma unroll
            for (int q = 0; q < 4; q++) acc[j][q] = 0.0f;

        // ---- wait producers of chunks 0,1 (cx 0..15), then prologue ---------
        if (tid < 16) {
            volatile unsigned* f = &g_flags[mh][tid][0];
            while (*f < tgt) { }
        }
        __syncthreads();
#pragma unroll
        for (int pc = 0; pc < 2; pc++) {
            uint32_t sa = sb0 + (uint32_t)(pc * A_STGB);
            int k0 = pc * KC;
#pragma unroll
            for (int i = 0; i < 2; i++) {
                int f = i * 512 + tid;
                int r = f >> 4, c = f & 15;
                cp16(sa + (uint32_t)(r * A_RB + c * 16),
                     hcur + (size_t)r * HH + k0 + c * 8);
            }
            CP_COMMIT();
        }

        // ---- main pipeline ----------------------------------------------------
        int stage = 0, nstage = 2;
        for (int kc = 0; kc < NCHUNK; kc++) {
            CP_WAIT1();
            // wait producers of chunk kc+2 (cx 8(kc+2)..+8) before issuing it
            if (kc + 2 < NCHUNK && tid < 8) {
                volatile unsigned* f = &g_flags[mh][(kc + 2) * 8 + tid][0];
                while (*f < tgt) { }
            }
            __syncthreads();

            if (kc + 2 < NCHUNK) {
                uint32_t sa = sb0 + (uint32_t)(nstage * A_STGB);
                int k0 = (kc + 2) * KC;
#pragma unroll
                for (int i = 0; i < 2; i++) {
                    int f = i * 512 + tid;
                    int r = f >> 4, c = f & 15;
                    cp16(sa + (uint32_t)(r * A_RB + c * 16),
                         hcur + (size_t)r * HH + k0 + c * 8);
                }
            }
            CP_COMMIT();

            const uint32_t su  = sb0 + (uint32_t)(stage * A_STGB);
            const uint32_t kbB = (uint32_t)(kc * 256);     // B chunk byte offset
#pragma unroll
            for (int kk = 0; kk < 8; kk++) {
                uint32_t a[4], b[4];
                ldsm4(a, su + offA + kk * 32);
                ldsm4(b, sb0 + offB + kbB + kk * 32);
#pragma unroll
                for (int nt = 0; nt < 2; nt++)
                    mma_f16(acc[nt], a, &b[nt * 2]);
            }

            stage = (stage == 2) ? 0 : stage + 1;
            nstage = (nstage == 2) ? 0 : nstage + 1;
        }

        // ---- shuffle epilogue: exchange gates within lane pairs ----------------
        {
            __half hv[2];
#pragma unroll
            for (int nt = 0; nt < 2; nt++) {
                float o0 = __shfl_xor_sync(0xffffffffu, acc[nt][0], 1);
                float o1 = __shfl_xor_sync(0xffffffffu, acc[nt][1], 1);
                float o2 = __shfl_xor_sync(0xffffffffu, acc[nt][2], 1);
                float o3 = __shfl_xor_sync(0xffffffffu, acc[nt][3], 1);

                float gf = odd ? o2 : acc[nt][0];
                float gi = odd ? o3 : acc[nt][1];
                float gg = odd ? acc[nt][2] : o0;
                float go = odd ? acc[nt][3] : o1;

                float2 xa = __half22float2(*(const __half2*)
                            (nt == 0 ? (const void*)&xwr0.x : (const void*)&xwr1.x));
                float2 xb = __half22float2(*(const __half2*)
                            (nt == 0 ? (const void*)&xwr0.y : (const void*)&xwr1.y));

                float f  = sigm(gf + xa.x);
                float ii = sigm(gi + xa.y);
                float g  = tanhf(gg + xb.x);
                float o  = sigm(go + xb.y);
                float cc = fmaf(f, c_reg[nt], ii * g);
                c_reg[nt] = cc;
                float h  = o * tanhf(cc);
                oacc[nt] += h;
                hv[nt]   = __float2half_rn(h);
            }
            __half* hn = g_hbuf[(t + 1) & 1]
                       + (size_t)(mrow0 + urow) * HH + cx * 16;
            hn[hl0]     = hv[0];
            hn[hl0 + 2] = hv[1];
        }

        // ---- publish progress (release: bar + leader fence) --------------------
        __syncthreads();
        if (tid == 0) {
            __threadfence();
            *(volatile unsigned*)&g_flags[mh][cx][0] = (unsigned)(t + 1);
        }
    }

    // final output: mean over time (2 scattered floats per lane)
    {
        const float inv = 1.0f / (float)SS;
        float* o = out + (size_t)(mrow0 + urow) * HH + cx * 16;
        o[hl0]     = oacc[0] * inv;
        o[hl0 + 2] = oacc[1] * inv;
    }
}

// ---------------------------------------------------------------------------
// Launch: 6 graph nodes
// ---------------------------------------------------------------------------
extern "C" void kernel_launch(void* const* d_in, const int* in_sizes, int n_in,
                              void* d_out, int out_size)
{
    const float* x    = (const float*)d_in[0];
    const float* W    = (const float*)d_in[1];
    const float* U    = (const float*)d_in[2];
    const float* bias = (const float*)d_in[3];
    float* out = (float*)d_out;

    static bool configured = false;
    if (!configured) {
        cudaFuncSetAttribute(lstm_mma,
                             cudaFuncAttributeMaxDynamicSharedMemorySize,
                             RSM_BYTES);
        configured = true;
    }

    lstm_init<<<512, 256>>>(bias);
    ut_prep<<<(int)(((size_t)GG * HH) / 256), 256>>>(U);
    wt_prep<<<(int)(((size_t)GG * II) / 256), 256>>>(W);
    x_prep<<<(int)(((size_t)BB * SS * II) / 1024), 256>>>(x);

    dim3 g1(SS * BB / 128, GG / 128);   // (512, 32)
    gemm_xw_mma<<<g1, 256>>>();

    lstm_mma<<<NB, NT, RSM_BYTES>>>(out);
}

// round 11
// speedup vs baseline: 1.2953x; 1.2953x over previous
#include <cuda_runtime.h>
#include <cuda_fp16.h>
#include <math.h>
#include <stdint.h>

// Problem constants
#define BB 128      // batch
#define SS 512      // seq len
#define II 512      // input dim
#define HH 1024     // hidden dim
#define GG 4096     // 4*H (gates)

#define NB 128      // persistent CTAs: 64 col-groups x 2 batch halves
#define NT 512      // threads per CTA (16 warps)

// ---------------------------------------------------------------------------
// Device scratch
// ---------------------------------------------------------------------------
__device__ __half   g_xwh[(size_t)SS * BB * GG];  // (s, b, n'=4h+g) fp16 : 0.5 GiB
__device__ __half   g_Uh[(size_t)GG * HH];        // U re-laid: [n'][k], fp16
__device__ __half   g_Whk[(size_t)GG * II];       // W re-laid: [n'][k], fp16
__device__ __half   g_xh[(size_t)BB * SS * II];   // x in fp16
__device__ float    g_biasI[GG];                  // bias interleaved n'=4h+g
__device__ __half   g_hbuf[2][BB * HH];           // double-buffered hidden (fp16)
__device__ unsigned g_bar;                        // single grid barrier counter

// ---------------------------------------------------------------------------
// Helpers
// ---------------------------------------------------------------------------
__device__ __forceinline__ float sigm(float v) { return 1.0f / (1.0f + __expf(-v)); }
__device__ __forceinline__ uint32_t smem_u32(const void* p) {
    uint32_t a;
    asm("{ .reg .u64 t; cvta.to.shared.u64 t, %1; cvt.u32.u64 %0, t; }"
        : "=r"(a) : "l"(p));
    return a;
}
__device__ __forceinline__ void mma_f16(float* d, const uint32_t* a, const uint32_t* b) {
    asm volatile(
        "mma.sync.aligned.m16n8k16.row.col.f32.f16.f16.f32 "
        "{%0,%1,%2,%3}, {%4,%5,%6,%7}, {%8,%9}, {%0,%1,%2,%3};"
        : "+f"(d[0]), "+f"(d[1]), "+f"(d[2]), "+f"(d[3])
        : "r"(a[0]), "r"(a[1]), "r"(a[2]), "r"(a[3]), "r"(b[0]), "r"(b[1]));
}
__device__ __forceinline__ void ldsm4(uint32_t* r, uint32_t addr) {
    asm volatile("ldmatrix.sync.aligned.m8n8.x4.shared.b16 {%0,%1,%2,%3}, [%4];"
        : "=r"(r[0]), "=r"(r[1]), "=r"(r[2]), "=r"(r[3]) : "r"(addr));
}
__device__ __forceinline__ void cp16(uint32_t s, const void* g) {
    asm volatile("cp.async.cg.shared.global [%0], [%1], 16;" :: "r"(s), "l"(g));
}
#define CP_COMMIT() asm volatile("cp.async.commit_group;" ::: "memory")
#define CP_WAIT1()  asm volatile("cp.async.wait_group 1;" ::: "memory")
#define CP_WAIT0()  asm volatile("cp.async.wait_group 0;" ::: "memory")

// ---------------------------------------------------------------------------
// init: zero h buffers + barrier; interleaved bias
// ---------------------------------------------------------------------------
__global__ void lstm_init(const float* __restrict__ bias) {
    int idx = blockIdx.x * blockDim.x + threadIdx.x; // 131072 threads
    ((uint32_t*)g_hbuf)[idx] = 0u;                   // both 256KB buffers
    if (idx == 0) g_bar = 0u;
    if (idx < GG) {
        int h = idx >> 2, g = idx & 3;
        g_biasI[idx] = bias[g * HH + h];
    }
}

// ---------------------------------------------------------------------------
// Preps: fp16 conversions / re-layouts
// ---------------------------------------------------------------------------
__global__ void ut_prep(const float* __restrict__ U) {
    size_t idx = (size_t)blockIdx.x * 256 + threadIdx.x; // 4M, idx = n'*1024+k
    int n = (int)(idx >> 10);
    int k = (int)(idx & 1023);
    int h = n >> 2, g = n & 3;
    g_Uh[idx] = __float2half_rn(U[(size_t)k * GG + g * HH + h]);
}
__global__ void wt_prep(const float* __restrict__ W) {
    size_t idx = (size_t)blockIdx.x * 256 + threadIdx.x; // 2M, idx = n'*512+k
    int n = (int)(idx >> 9);
    int k = (int)(idx & 511);
    int h = n >> 2, g = n & 3;
    g_Whk[idx] = __float2half_rn(W[(size_t)k * GG + g * HH + h]);
}
__global__ void x_prep(const float* __restrict__ x) {
    size_t i4 = (size_t)blockIdx.x * 256 + threadIdx.x; // 8.4M, 4 floats each
    float4 v = *(const float4*)(x + i4 * 4);
    __half2 a = __floats2half2_rn(v.x, v.y);
    __half2 b = __floats2half2_rn(v.z, v.w);
    *(uint2*)(g_xh + i4 * 4) = make_uint2(*(uint32_t*)&a, *(uint32_t*)&b);
}

// ---------------------------------------------------------------------------
// GEMM 1 via mma.sync fp16: xW = x @ W + bias -> g_xwh (fp16, interleaved n')
// ---------------------------------------------------------------------------
#define G_RB 80     // row bytes (32 data halves + 8 pad)

__global__ __launch_bounds__(256) void gemm_xw_mma(void)
{
    __shared__ __half As[128 * 40];
    __shared__ __half Bs[128 * 40];
    const uint32_t sA = smem_u32(As);
    const uint32_t sB = smem_u32(Bs);

    const int tid  = threadIdx.x;
    const int wid  = tid >> 5;
    const int lane = tid & 31;
    const int qr = lane >> 2;
    const int qc = lane & 3;

    const int m0 = blockIdx.x * 128;
    const int n0 = blockIdx.y * 128;
    const int m0w = (wid & 1) * 64;
    const int n0w = (wid >> 1) * 32;

    const uint32_t offA = (uint32_t)((m0w + (lane & 15)) * G_RB + (lane >> 4) * 16);
    const uint32_t offB = (uint32_t)((n0w + ((lane >> 4) << 3) + (lane & 7)) * G_RB
                                     + ((lane >> 3) & 1) * 16);

    float acc[4][4][4];
#pragma unroll
    for (int i = 0; i < 4; i++)
#pragma unroll
        for (int j = 0; j < 4; j++)
#pragma unroll
            for (int q = 0; q < 4; q++) acc[i][j][q] = 0.0f;

    for (int k0 = 0; k0 < II; k0 += 32) {
#pragma unroll
        for (int i = 0; i < 2; i++) {
            int f = i * 256 + tid;
            int r = f >> 2, c = f & 3;
            *(uint4*)((char*)As + r * G_RB + c * 16) =
                *(const uint4*)&g_xh[(size_t)(m0 + r) * II + k0 + c * 8];
        }
#pragma unroll
        for (int i = 0; i < 2; i++) {
            int f = i * 256 + tid;
            int r = f >> 2, c = f & 3;
            *(uint4*)((char*)Bs + r * G_RB + c * 16) =
                *(const uint4*)&g_Whk[(size_t)(n0 + r) * II + k0 + c * 8];
        }
        __syncthreads();

#pragma unroll
        for (int kk = 0; kk < 2; kk++) {
            const uint32_t kb = kk * 32;
            uint32_t a[4][4], b[2][4];
#pragma unroll
            for (int mt = 0; mt < 4; mt++)
                ldsm4(a[mt], sA + offA + mt * 16 * G_RB + kb);
            ldsm4(b[0], sB + offB + kb);
            ldsm4(b[1], sB + offB + 16 * G_RB + kb);
#pragma unroll
            for (int mt = 0; mt < 4; mt++)
#pragma unroll
                for (int nt = 0; nt < 4; nt++)
                    mma_f16(acc[mt][nt], a[mt], &b[nt >> 1][(nt & 1) * 2]);
        }
        __syncthreads();
    }

    // epilogue: + biasI, fp16 pack, scatter to g_xwh[(s*BB+b)*GG + n']
#pragma unroll
    for (int nt = 0; nt < 4; nt++) {
        int col = n0 + n0w + nt * 8 + qc * 2;
        float2 bv = *(const float2*)&g_biasI[col];
#pragma unroll
        for (int mt = 0; mt < 4; mt++) {
            int r1 = m0 + m0w + mt * 16 + qr;
            int r2 = r1 + 8;
            int b1 = r1 >> 9, s1 = r1 & 511;
            int b2 = r2 >> 9, s2 = r2 & 511;
            size_t d1 = ((size_t)s1 * BB + b1) * GG + col;
            size_t d2 = ((size_t)s2 * BB + b2) * GG + col;
            *(__half2*)&g_xwh[d1] = __floats2half2_rn(acc[mt][nt][0] + bv.x,
                                                      acc[mt][nt][1] + bv.y);
            *(__half2*)&g_xwh[d2] = __floats2half2_rn(acc[mt][nt][2] + bv.x,
                                                      acc[mt][nt][3] + bv.y);
        }
    }
}

// ---------------------------------------------------------------------------
// Persistent recurrence (R8 structure, proven 5430us): 128 CTAs, 16 warps,
// single grid barrier, S-smem staging epilogue, coalesced uint32 h stores.
// Only change vs R8: xW is fp16 (one uint4 prefetch per thread).
// ---------------------------------------------------------------------------
#define KC       128
#define NCHUNK   8
#define A_RB     272                    // 64 rows x (256 data + 16 pad) bytes
#define A_STGB   (64 * A_RB)            // 17408
#define B_RB     2064
#define B_OFF    (3 * A_STGB)           // 52224
#define S_OFFB   (B_OFF + 64 * B_RB)    // 184320
#define RST      68
#define RSM_BYTES (S_OFFB + 64 * RST * 4)   // 201728

__global__ __launch_bounds__(NT, 1) void lstm_mma(float* __restrict__ out)
{
    extern __shared__ char smc[];
    const uint32_t sb0 = smem_u32(smc);
    float* S = (float*)(smc + S_OFFB);

    const int tid  = threadIdx.x;
    const int wid  = tid >> 5;
    const int lane = tid & 31;
    const int qr = lane >> 2;
    const int qc = lane & 3;
    const int cx = blockIdx.x >> 1;     // column group 0..63
    const int mh = blockIdx.x & 1;      // batch half 0..1

    const int m0w = (wid & 3) * 16;     // warp rows (0,16,32,48)
    const int n0w = (wid >> 2) * 16;    // warp cols (0,16,32,48)

    // ldmatrix lane offsets
    const uint32_t offA = (uint32_t)((m0w + (lane & 15)) * A_RB + (lane >> 4) * 16);
    const uint32_t offB = (uint32_t)(B_OFF +
        (n0w + ((lane >> 4) << 3) + (lane & 7)) * B_RB + ((lane >> 3) & 1) * 16);

    const __half* Up = g_Uh + (size_t)cx * 64 * HH;
    const int mrow0 = mh * 64;          // first batch row

    // update-phase mapping: thread -> batch row, 2 hidden units (8 gates)
    const int ub   = tid >> 3;          // 0..63 (local batch row)
    const int hof  = (tid & 7) * 2;     // local hidden unit 0..14 (2 per thread)

    float c_reg[2], oacc[2];
    c_reg[0] = c_reg[1] = oacc[0] = oacc[1] = 0.f;

    // ---- one-time: U slice into persistent smem (8192 x 16B, 16/thread) ----
#pragma unroll
    for (int i = 0; i < 16; i++) {
        int f = i * 512 + tid;
        int r = f >> 7, c = f & 127;
        cp16(sb0 + (uint32_t)(B_OFF + r * B_RB + c * 16),
             Up + (size_t)r * HH + c * 8);
    }
    CP_COMMIT();
    CP_WAIT0();
    __syncthreads();

    for (int t = 0; t < SS; t++) {
        const __half* hcur = g_hbuf[t & 1] + (size_t)mrow0 * HH;

        // prefetch xw (fp16): 8 gates = 8 halves = one uint4 per thread
        uint4 xwr;
        {
            const __half* xp = g_xwh + ((size_t)t * BB + mrow0 + ub) * GG
                             + cx * 64 + hof * 4;
            xwr = __ldg((const uint4*)xp);
        }

        float acc[2][4];
#pragma unroll
        for (int j = 0; j < 2; j++)
#pragma unroll
            for (int q = 0; q < 4; q++) acc[j][q] = 0.0f;

        // ---- prologue: A chunks 0,1 (1024 x 16B, 2/thread each) -------------
#pragma unroll
        for (int pc = 0; pc < 2; pc++) {
            uint32_t sa = sb0 + (uint32_t)(pc * A_STGB);
            int k0 = pc * KC;
#pragma unroll
            for (int i = 0; i < 2; i++) {
                int f = i * 512 + tid;
                int r = f >> 4, c = f & 15;
                cp16(sa + (uint32_t)(r * A_RB + c * 16),
                     hcur + (size_t)r * HH + k0 + c * 8);
            }
            CP_COMMIT();
        }

        // ---- main pipeline ----------------------------------------------------
        int stage = 0, nstage = 2;
        for (int kc = 0; kc < NCHUNK; kc++) {
            CP_WAIT1();
            __syncthreads();

            if (kc + 2 < NCHUNK) {
                uint32_t sa = sb0 + (uint32_t)(nstage * A_STGB);
                int k0 = (kc + 2) * KC;
#pragma unroll
                for (int i = 0; i < 2; i++) {
                    int f = i * 512 + tid;
                    int r = f >> 4, c = f & 15;
                    cp16(sa + (uint32_t)(r * A_RB + c * 16),
                         hcur + (size_t)r * HH + k0 + c * 8);
                }
            }
            CP_COMMIT();

            const uint32_t su  = sb0 + (uint32_t)(stage * A_STGB);
            const uint32_t kbB = (uint32_t)(kc * 256);     // B chunk byte offset
#pragma unroll
            for (int kk = 0; kk < 8; kk++) {
                uint32_t a[4], b[4];
                ldsm4(a, su + offA + kk * 32);
                ldsm4(b, sb0 + offB + kbB + kk * 32);
#pragma unroll
                for (int nt = 0; nt < 2; nt++)
                    mma_f16(acc[nt], a, &b[nt * 2]);
            }

            stage = (stage == 2) ? 0 : stage + 1;
            nstage = (nstage == 2) ? 0 : nstage + 1;
        }

        // ---- stage C -> S --------------------------------------------------------
        __syncthreads();
#pragma unroll
        for (int nt = 0; nt < 2; nt++) {
            int row = m0w + qr;
            int col = n0w + nt * 8 + qc * 2;
            *(float2*)&S[row * RST + col] = make_float2(acc[nt][0], acc[nt][1]);
            *(float2*)&S[(row + 8) * RST + col] = make_float2(acc[nt][2], acc[nt][3]);
        }
        __syncthreads();

        // ---- fused cell update ----------------------------------------------------
        {
            const float* Sr = S + ub * RST + hof * 4;
            float4 sv0 = *(const float4*)&Sr[0];
            float4 sv1 = *(const float4*)&Sr[4];
            float2 xa0 = __half22float2(*(const __half2*)&xwr.x);  // f,i unit0
            float2 xb0 = __half22float2(*(const __half2*)&xwr.y);  // g,o unit0
            float2 xa1 = __half22float2(*(const __half2*)&xwr.z);  // f,i unit1
            float2 xb1 = __half22float2(*(const __half2*)&xwr.w);  // g,o unit1
            __half hv[2];
            {
                float f  = sigm(sv0.x + xa0.x);
                float ii = sigm(sv0.y + xa0.y);
                float g  = tanhf(sv0.z + xb0.x);
                float o  = sigm(sv0.w + xb0.y);
                float cc = fmaf(f, c_reg[0], ii * g);
                c_reg[0] = cc;
                float h  = o * tanhf(cc);
                oacc[0] += h;
                hv[0]    = __float2half_rn(h);
            }
            {
                float f  = sigm(sv1.x + xa1.x);
                float ii = sigm(sv1.y + xa1.y);
                float g  = tanhf(sv1.z + xb1.x);
                float o  = sigm(sv1.w + xb1.y);
                float cc = fmaf(f, c_reg[1], ii * g);
                c_reg[1] = cc;
                float h  = o * tanhf(cc);
                oacc[1] += h;
                hv[1]    = __float2half_rn(h);
            }
            __half* hn = g_hbuf[(t + 1) & 1]
                       + (size_t)(mrow0 + ub) * HH + cx * 16 + hof;
            *(uint32_t*)hn = *(uint32_t*)hv;    // 2 halves, 4B aligned
        }

        // ---- grid barrier (leader-only fences; bar.sync is cumulative) -----------
        __syncthreads();
        if (tid == 0) {
            __threadfence();                // release all CTA writes
            atomicAdd(&g_bar, 1u);
            unsigned tgt = (unsigned)(t + 1) * NB;
            while (*(volatile unsigned*)&g_bar < tgt) { }
            __threadfence();                // acquire
        }
        __syncthreads();
    }

    // final output: mean over time (2 floats per thread)
    {
        const float inv = 1.0f / (float)SS;
        *(float2*)(out + (size_t)(mrow0 + ub) * HH + cx * 16 + hof) =
            make_float2(oacc[0] * inv, oacc[1] * inv);
    }
}

// ---------------------------------------------------------------------------
// Launch: 6 graph nodes
// ---------------------------------------------------------------------------
extern "C" void kernel_launch(void* const* d_in, const int* in_sizes, int n_in,
                              void* d_out, int out_size)
{
    const float* x    = (const float*)d_in[0];
    const float* W    = (const float*)d_in[1];
    const float* U    = (const float*)d_in[2];
    const float* bias = (const float*)d_in[3];
    float* out = (float*)d_out;

    static bool configured = false;
    if (!configured) {
        cudaFuncSetAttribute(lstm_mma,
                             cudaFuncAttributeMaxDynamicSharedMemorySize,
                             RSM_BYTES);
        configured = true;
    }

    lstm_init<<<512, 256>>>(bias);
    ut_prep<<<(int)(((size_t)GG * HH) / 256), 256>>>(U);
    wt_prep<<<(int)(((size_t)GG * II) / 256), 256>>>(W);
    x_prep<<<(int)(((size_t)BB * SS * II) / 1024), 256>>>(x);

    dim3 g1(SS * BB / 128, GG / 128);   // (512, 32)
    gemm_xw_mma<<<g1, 256>>>();

    lstm_mma<<<NB, NT, RSM_BYTES>>>(out);
}

// round 12
// speedup vs baseline: 1.3399x; 1.0344x over previous
#include <cuda_runtime.h>
#include <cuda_fp16.h>
#include <math.h>
#include <stdint.h>

// Problem constants
#define BB 128      // batch
#define SS 512      // seq len
#define II 512      // input dim
#define HH 1024     // hidden dim
#define GG 4096     // 4*H (gates)

#define NB 128      // persistent CTAs: 64 col-groups x 2 batch halves
#define NT 512      // threads per CTA (16 warps)

// ---------------------------------------------------------------------------
// Device scratch
// ---------------------------------------------------------------------------
__device__ __half   g_xwh[(size_t)SS * BB * GG];  // (s, b, n'=4h+g) fp16 : 0.5 GiB
__device__ __half   g_Uh[(size_t)GG * HH];        // U re-laid: [n'][k], fp16
__device__ __half   g_Whk[(size_t)GG * II];       // W re-laid: [n'][k], fp16
__device__ __half   g_xh[(size_t)BB * SS * II];   // x in fp16
__device__ float    g_biasI[GG];                  // bias interleaved n'=4h+g
__device__ __half   g_hbuf[2][BB * HH];           // double-buffered hidden (fp16)
__device__ unsigned g_bar;                        // single grid barrier counter

// ---------------------------------------------------------------------------
// Helpers
// ---------------------------------------------------------------------------
__device__ __forceinline__ float sigm(float v) {
    return __fdividef(1.0f, 1.0f + __expf(-v));
}
__device__ __forceinline__ float tanh_fast(float v) {
    // clamped exp-based tanh: ~3 MUFU, fp32-accurate, no inf/inf NaN
    v = fminf(fmaxf(v, -15.0f), 15.0f);
    float e = __expf(-2.0f * v);
    return __fdividef(1.0f - e, 1.0f + e);
}
__device__ __forceinline__ uint32_t smem_u32(const void* p) {
    uint32_t a;
    asm("{ .reg .u64 t; cvta.to.shared.u64 t, %1; cvt.u32.u64 %0, t; }"
        : "=r"(a) : "l"(p));
    return a;
}
__device__ __forceinline__ void mma_f16(float* d, const uint32_t* a, const uint32_t* b) {
    asm volatile(
        "mma.sync.aligned.m16n8k16.row.col.f32.f16.f16.f32 "
        "{%0,%1,%2,%3}, {%4,%5,%6,%7}, {%8,%9}, {%0,%1,%2,%3};"
        : "+f"(d[0]), "+f"(d[1]), "+f"(d[2]), "+f"(d[3])
        : "r"(a[0]), "r"(a[1]), "r"(a[2]), "r"(a[3]), "r"(b[0]), "r"(b[1]));
}
__device__ __forceinline__ void ldsm4(uint32_t* r, uint32_t addr) {
    asm volatile("ldmatrix.sync.aligned.m8n8.x4.shared.b16 {%0,%1,%2,%3}, [%4];"
        : "=r"(r[0]), "=r"(r[1]), "=r"(r[2]), "=r"(r[3]) : "r"(addr));
}
__device__ __forceinline__ void cp16(uint32_t s, const void* g) {
    asm volatile("cp.async.cg.shared.global [%0], [%1], 16;" :: "r"(s), "l"(g));
}
#define CP_COMMIT() asm volatile("cp.async.commit_group;" ::: "memory")
#define CP_WAIT1()  asm volatile("cp.async.wait_group 1;" ::: "memory")
#define CP_WAIT0()  asm volatile("cp.async.wait_group 0;" ::: "memory")

// ---------------------------------------------------------------------------
// Merged prep: x->fp16, U/W re-layout+fp16, bias interleave, h zero, barrier.
// All writes independent. Grid 32768 x 256 = 8.39M threads.
// ---------------------------------------------------------------------------
__global__ void prep_all(const float* __restrict__ x,
                         const float* __restrict__ W,
                         const float* __restrict__ U,
                         const float* __restrict__ bias)
{
    size_t idx = (size_t)blockIdx.x * 256 + threadIdx.x;

    // x: 8388608 float4 -> fp16
    {
        float4 v = *(const float4*)(x + idx * 4);
        __half2 a = __floats2half2_rn(v.x, v.y);
        __half2 b = __floats2half2_rn(v.z, v.w);
        *(uint2*)(g_xh + idx * 4) = make_uint2(*(uint32_t*)&a, *(uint32_t*)&b);
    }
    // U re-layout: 4M elems, idx = n'*1024 + k
    if (idx < (size_t)GG * HH) {
        int n = (int)(idx >> 10);
        int k = (int)(idx & 1023);
        int h = n >> 2, g = n & 3;
        g_Uh[idx] = __float2half_rn(U[(size_t)k * GG + g * HH + h]);
    }
    // W re-layout: 2M elems, idx = n'*512 + k
    if (idx < (size_t)GG * II) {
        int n = (int)(idx >> 9);
        int k = (int)(idx & 511);
        int h = n >> 2, g = n & 3;
        g_Whk[idx] = __float2half_rn(W[(size_t)k * GG + g * HH + h]);
    }
    // zero both h buffers (as uint32 words)
    if (idx < 131072) ((uint32_t*)g_hbuf)[idx] = 0u;
    // interleaved bias
    if (idx < GG) {
        int h = (int)(idx >> 2), g = (int)(idx & 3);
        g_biasI[idx] = bias[g * HH + h];
    }
    if (idx == 0) g_bar = 0u;
}

// ---------------------------------------------------------------------------
// GEMM 1 via mma.sync fp16: xW = x @ W + bias -> g_xwh (fp16, interleaved n')
// ---------------------------------------------------------------------------
#define G_RB 80     // row bytes (32 data halves + 8 pad)

__global__ __launch_bounds__(256) void gemm_xw_mma(void)
{
    __shared__ __half As[128 * 40];
    __shared__ __half Bs[128 * 40];
    const uint32_t sA = smem_u32(As);
    const uint32_t sB = smem_u32(Bs);

    const int tid  = threadIdx.x;
    const int wid  = tid >> 5;
    const int lane = tid & 31;
    const int qr = lane >> 2;
    const int qc = lane & 3;

    const int m0 = blockIdx.x * 128;
    const int n0 = blockIdx.y * 128;
    const int m0w = (wid & 1) * 64;
    const int n0w = (wid >> 1) * 32;

    const uint32_t offA = (uint32_t)((m0w + (lane & 15)) * G_RB + (lane >> 4) * 16);
    const uint32_t offB = (uint32_t)((n0w + ((lane >> 4) << 3) + (lane & 7)) * G_RB
                                     + ((lane >> 3) & 1) * 16);

    float acc[4][4][4];
#pragma unroll
    for (int i = 0; i < 4; i++)
#pragma unroll
        for (int j = 0; j < 4; j++)
#pragma unroll
            for (int q = 0; q < 4; q++) acc[i][j][q] = 0.0f;

    for (int k0 = 0; k0 < II; k0 += 32) {
#pragma unroll
        for (int i = 0; i < 2; i++) {
            int f = i * 256 + tid;
            int r = f >> 2, c = f & 3;
            *(uint4*)((char*)As + r * G_RB + c * 16) =
                *(const uint4*)&g_xh[(size_t)(m0 + r) * II + k0 + c * 8];
        }
#pragma unroll
        for (int i = 0; i < 2; i++) {
            int f = i * 256 + tid;
            int r = f >> 2, c = f & 3;
            *(uint4*)((char*)Bs + r * G_RB + c * 16) =
                *(const uint4*)&g_Whk[(size_t)(n0 + r) * II + k0 + c * 8];
        }
        __syncthreads();

#pragma unroll
        for (int kk = 0; kk < 2; kk++) {
            const uint32_t kb = kk * 32;
            uint32_t a[4][4], b[2][4];
#pragma unroll
            for (int mt = 0; mt < 4; mt++)
                ldsm4(a[mt], sA + offA + mt * 16 * G_RB + kb);
            ldsm4(b[0], sB + offB + kb);
            ldsm4(b[1], sB + offB + 16 * G_RB + kb);
#pragma unroll
            for (int mt = 0; mt < 4; mt++)
#pragma unroll
                for (int nt = 0; nt < 4; nt++)
                    mma_f16(acc[mt][nt], a[mt], &b[nt >> 1][(nt & 1) * 2]);
        }
        __syncthreads();
    }

    // epilogue: + biasI, fp16 pack, scatter to g_xwh[(s*BB+b)*GG + n']
#pragma unroll
    for (int nt = 0; nt < 4; nt++) {
        int col = n0 + n0w + nt * 8 + qc * 2;
        float2 bv = *(const float2*)&g_biasI[col];
#pragma unroll
        for (int mt = 0; mt < 4; mt++) {
            int r1 = m0 + m0w + mt * 16 + qr;
            int r2 = r1 + 8;
            int b1 = r1 >> 9, s1 = r1 & 511;
            int b2 = r2 >> 9, s2 = r2 & 511;
            size_t d1 = ((size_t)s1 * BB + b1) * GG + col;
            size_t d2 = ((size_t)s2 * BB + b2) * GG + col;
            *(__half2*)&g_xwh[d1] = __floats2half2_rn(acc[mt][nt][0] + bv.x,
                                                      acc[mt][nt][1] + bv.y);
            *(__half2*)&g_xwh[d2] = __floats2half2_rn(acc[mt][nt][2] + bv.x,
                                                      acc[mt][nt][3] + bv.y);
        }
    }
}

// ---------------------------------------------------------------------------
// Persistent recurrence (R11 structure, proven 5309us): 128 CTAs, 16 warps,
// single grid barrier, S-smem staging epilogue, coalesced uint32 h stores.
// R12 deltas: fast exp-based tanh; xW prefetch for step t issued right after
// the MMA loop of step t (hidden under epilogue+barrier instead of exposed
// at the next loop top).
// ---------------------------------------------------------------------------
#define KC       128
#define NCHUNK   8
#define A_RB     272                    // 64 rows x (256 data + 16 pad) bytes
#define A_STGB   (64 * A_RB)            // 17408
#define B_RB     2064
#define B_OFF    (3 * A_STGB)           // 52224
#define S_OFFB   (B_OFF + 64 * B_RB)    // 184320
#define RST      68
#define RSM_BYTES (S_OFFB + 64 * RST * 4)   // 201728

__global__ __launch_bounds__(NT, 1) void lstm_mma(float* __restrict__ out)
{
    extern __shared__ char smc[];
    const uint32_t sb0 = smem_u32(smc);
    float* S = (float*)(smc + S_OFFB);

    const int tid  = threadIdx.x;
    const int wid  = tid >> 5;
    const int lane = tid & 31;
    const int qr = lane >> 2;
    const int qc = lane & 3;
    const int cx = blockIdx.x >> 1;     // column group 0..63
    const int mh = blockIdx.x & 1;      // batch half 0..1

    const int m0w = (wid & 3) * 16;     // warp rows (0,16,32,48)
    const int n0w = (wid >> 2) * 16;    // warp cols (0,16,32,48)

    // ldmatrix lane offsets
    const uint32_t offA = (uint32_t)((m0w + (lane & 15)) * A_RB + (lane >> 4) * 16);
    const uint32_t offB = (uint32_t)(B_OFF +
        (n0w + ((lane >> 4) << 3) + (lane & 7)) * B_RB + ((lane >> 3) & 1) * 16);

    const __half* Up = g_Uh + (size_t)cx * 64 * HH;
    const int mrow0 = mh * 64;          // first batch row

    // update-phase mapping: thread -> batch row, 2 hidden units (8 gates)
    const int ub   = tid >> 3;          // 0..63 (local batch row)
    const int hof  = (tid & 7) * 2;     // local hidden unit (2 per thread)

    // per-thread xw pointer (fp16, one uint4 = 8 gates per step)
    const __half* xwbase = g_xwh + ((size_t)(mrow0 + ub)) * GG + cx * 64 + hof * 4;

    float c_reg[2], oacc[2];
    c_reg[0] = c_reg[1] = oacc[0] = oacc[1] = 0.f;

    // ---- one-time: U slice into persistent smem (8192 x 16B, 16/thread) ----
#pragma unroll
    for (int i = 0; i < 16; i++) {
        int f = i * 512 + tid;
        int r = f >> 7, c = f & 127;
        cp16(sb0 + (uint32_t)(B_OFF + r * B_RB + c * 16),
             Up + (size_t)r * HH + c * 8);
    }
    CP_COMMIT();
    CP_WAIT0();
    __syncthreads();

    // prefetch xw for step 0
    uint4 xwr = __ldg((const uint4*)xwbase);

    for (int t = 0; t < SS; t++) {
        const __half* hcur = g_hbuf[t & 1] + (size_t)mrow0 * HH;

        float acc[2][4];
#pragma unroll
        for (int j = 0; j < 2; j++)
#pragma unroll
            for (int q = 0; q < 4; q++) acc[j][q] = 0.0f;

        // ---- prologue: A chunks 0,1 (1024 x 16B, 2/thread each) -------------
#pragma unroll
        for (int pc = 0; pc < 2; pc++) {
            uint32_t sa = sb0 + (uint32_t)(pc * A_STGB);
            int k0 = pc * KC;
#pragma unroll
            for (int i = 0; i < 2; i++) {
                int f = i * 512 + tid;
                int r = f >> 4, c = f & 15;
                cp16(sa + (uint32_t)(r * A_RB + c * 16),
                     hcur + (size_t)r * HH + k0 + c * 8);
            }
            CP_COMMIT();
        }

        // ---- main pipeline ----------------------------------------------------
        int stage = 0, nstage = 2;
        for (int kc = 0; kc < NCHUNK; kc++) {
            CP_WAIT1();
            __syncthreads();

            if (kc + 2 < NCHUNK) {
                uint32_t sa = sb0 + (uint32_t)(nstage * A_STGB);
                int k0 = (kc + 2) * KC;
#pragma unroll
                for (int i = 0; i < 2; i++) {
                    int f = i * 512 + tid;
                    int r = f >> 4, c = f & 15;
                    cp16(sa + (uint32_t)(r * A_RB + c * 16),
                         hcur + (size_t)r * HH + k0 + c * 8);
                }
            }
            CP_COMMIT();

            const uint32_t su  = sb0 + (uint32_t)(stage * A_STGB);
            const uint32_t kbB = (uint32_t)(kc * 256);     // B chunk byte offset
#pragma unroll
            for (int kk = 0; kk < 8; kk++) {
                uint32_t a[4], b[4];
                ldsm4(a, su + offA + kk * 32);
                ldsm4(b, sb0 + offB + kbB + kk * 32);
#pragma unroll
                for (int nt = 0; nt < 2; nt++)
                    mma_f16(acc[nt], a, &b[nt * 2]);
            }

            stage = (stage == 2) ? 0 : stage + 1;
            nstage = (nstage == 2) ? 0 : nstage + 1;
        }

        // ---- stage C -> S --------------------------------------------------------
        __syncthreads();
#pragma unroll
        for (int nt = 0; nt < 2; nt++) {
            int row = m0w + qr;
            int col = n0w + nt * 8 + qc * 2;
            *(float2*)&S[row * RST + col] = make_float2(acc[nt][0], acc[nt][1]);
            *(float2*)&S[(row + 8) * RST + col] = make_float2(acc[nt][2], acc[nt][3]);
        }
        __syncthreads();

        // ---- fused cell update ----------------------------------------------------
        {
            const float* Sr = S + ub * RST + hof * 4;
            float4 sv0 = *(const float4*)&Sr[0];
            float4 sv1 = *(const float4*)&Sr[4];
            float2 xa0 = __half22float2(*(const __half2*)&xwr.x);  // f,i unit0
            float2 xb0 = __half22float2(*(const __half2*)&xwr.y);  // g,o unit0
            float2 xa1 = __half22float2(*(const __half2*)&xwr.z);  // f,i unit1
            float2 xb1 = __half22float2(*(const __half2*)&xwr.w);  // g,o unit1
            __half hv[2];
            {
                float f  = sigm(sv0.x + xa0.x);
                float ii = sigm(sv0.y + xa0.y);
                float g  = tanh_fast(sv0.z + xb0.x);
                float o  = sigm(sv0.w + xb0.y);
                float cc = fmaf(f, c_reg[0], ii * g);
                c_reg[0] = cc;
                float h  = o * tanh_fast(cc);
                oacc[0] += h;
                hv[0]    = __float2half_rn(h);
            }
            {
                float f  = sigm(sv1.x + xa1.x);
                float ii = sigm(sv1.y + xa1.y);
                float g  = tanh_fast(sv1.z + xb1.x);
                float o  = sigm(sv1.w + xb1.y);
                float cc = fmaf(f, c_reg[1], ii * g);
                c_reg[1] = cc;
                float h  = o * tanh_fast(cc);
                oacc[1] += h;
                hv[1]    = __float2half_rn(h);
            }
            __half* hn = g_hbuf[(t + 1) & 1]
                       + (size_t)(mrow0 + ub) * HH + cx * 16 + hof;
            *(uint32_t*)hn = *(uint32_t*)hv;    // 2 halves, 4B aligned
        }

        // prefetch xw for step t+1 (independent of barrier; hides L2/DRAM lat)
        if (t + 1 < SS)
            xwr = __ldg((const uint4*)(xwbase + (size_t)(t + 1) * BB * GG));

        // ---- grid barrier (leader-only fences; bar.sync is cumulative) -----------
        __syncthreads();
        if (tid == 0) {
            __threadfence();                // release all CTA writes
            atomicAdd(&g_bar, 1u);
            unsigned tgt = (unsigned)(t + 1) * NB;
            while (*(volatile unsigned*)&g_bar < tgt) { }
            __threadfence();                // acquire
        }
        __syncthreads();
    }

    // final output: mean over time (2 floats per thread)
    {
        const float inv = 1.0f / (float)SS;
        *(float2*)(out + (size_t)(mrow0 + ub) * HH + cx * 16 + hof) =
            make_float2(oacc[0] * inv, oacc[1] * inv);
    }
}

// ---------------------------------------------------------------------------
// Launch: 3 graph nodes
// ---------------------------------------------------------------------------
extern "C" void kernel_launch(void* const* d_in, const int* in_sizes, int n_in,
                              void* d_out, int out_size)
{
    const float* x    = (const float*)d_in[0];
    const float* W    = (const float*)d_in[1];
    const float* U    = (const float*)d_in[2];
    const float* bias = (const float*)d_in[3];
    float* out = (float*)d_out;

    static bool configured = false;
    if (!configured) {
        cudaFuncSetAttribute(lstm_mma,
                             cudaFuncAttributeMaxDynamicSharedMemorySize,
                             RSM_BYTES);
        configured = true;
    }

    prep_all<<<32768, 256>>>(x, W, U, bias);

    dim3 g1(SS * BB / 128, GG / 128);   // (512, 32)
    gemm_xw_mma<<<g1, 256>>>();

    lstm_mma<<<NB, NT, RSM_BYTES>>>(out);
}